// round 3
// baseline (speedup 1.0000x reference)
#include <cuda_runtime.h>
#include <cstdint>

// MultiLIF: I[B=32, L=2048, K=512] -> (spikes[B,L,K], spike_series[B,L,K])
// d_out: spikes (B*L*K floats) then spike_series (B*L*K floats).
//
// R3 changes vs R2 (150us):
//  - float2: each thread owns neurons (k, k+1) -> 2 independent chains (ILP=2),
//    LDG.64/STG.64, arithmetic per-lane identical to R2 (rel_err stays 0).
//  - pointer-increment addressing: in-batch store/load addresses are [R+imm],
//    no per-step int64 IMAD chains.
//  - 128 blocks x 64 threads: 2 warps/SM over 128 SMs (memory spread wide,
//    2 SMSPs/SM each running one warp with 2 chains of ILP).

static constexpr int B_ = 32;
static constexpr int L_ = 2048;
static constexpr int K_ = 512;
static constexpr int K2 = K_ / 2;            // float2 elements per timestep row
static constexpr int UNROLL = 16;            // timesteps per prefetch batch
static constexpr int STRIDE2 = UNROLL * K2;  // float2 elems per batch
static constexpr int NTHREADS = B_ * K2;     // 8192

__device__ __forceinline__ float div_const_rn(float x, float b, float y)
{
    // Markstein correctly-rounded x/b (y = RN(1/b)); branch-free, == __fdiv_rn
    // for all normal inputs reachable here.
    float q0 = __fmul_rn(x, y);
    float r  = __fmaf_rn(-b, q0, x);
    return __fmaf_rn(r, y, q0);
}

__device__ __forceinline__ void lif_step1(float It, float& v, float& a,
                                          float& n, float& s_out)
{
    float th = 1.0f + 1.5f * a;
    v = (v - div_const_rn(v, 20.0f, 0.05f)) + It;
    bool fire = (v >= th);
    float s = fire ? 1.0f : 0.0f;
    n = n + s;
    v = fire ? -0.5f : v;
    a = (a - div_const_rn(a, 100.0f, 0.01f)) + s;
    s_out = s;
}

__device__ __forceinline__ void lif_steps2(
    const float2* __restrict__ buf,
    float2* __restrict__ sp, float2* __restrict__ np,
    float2& v, float2& a, float2& n)
{
#pragma unroll
    for (int u = 0; u < UNROLL; u++) {
        float2 It = buf[u];
        float2 s;
        lif_step1(It.x, v.x, a.x, n.x, s.x);
        lif_step1(It.y, v.y, a.y, n.y, s.y);
        __stcs(sp + u * K2, s);
        __stcs(np + u * K2, n);
    }
}

__device__ __forceinline__ void load_batch2(
    const float2* __restrict__ ip, float2* __restrict__ buf)
{
#pragma unroll
    for (int u = 0; u < UNROLL; u++)
        buf[u] = __ldcs(ip + u * K2);
}

__global__ __launch_bounds__(64, 1)
void MultiLIF_kernel(const float2* __restrict__ I,
                     float2* __restrict__ spikes,
                     float2* __restrict__ series)
{
    int gid = blockIdx.x * blockDim.x + threadIdx.x;   // 0..8191
    int b  = gid >> 8;            // /256
    int kp = gid & (K2 - 1);      // float2 column

    int64_t base = (int64_t)b * L_ * K2 + kp;
    const float2* ip = I + base;
    float2* sp = spikes + base;
    float2* np = series + base;

    float2 v = {0.f, 0.f}, a = {0.f, 0.f}, n = {0.f, 0.f};

    float2 buf0[UNROLL], buf1[UNROLL];

    load_batch2(ip, buf0);
    const float2* ipn = ip + STRIDE2;

    constexpr int ITERS = L_ / (2 * UNROLL);   // 64
#pragma unroll 1
    for (int it = 0; it < ITERS; it++) {
        load_batch2(ipn, buf1);
        ipn += STRIDE2;
        lif_steps2(buf0, sp, np, v, a, n);
        sp += STRIDE2; np += STRIDE2;

        // last prefetch would run past the end; re-read a safe address instead
        const float2* pf = (it + 1 < ITERS) ? ipn : ip;
        load_batch2(pf, buf0);
        ipn += STRIDE2;
        lif_steps2(buf1, sp, np, v, a, n);
        sp += STRIDE2; np += STRIDE2;
    }
}

extern "C" void kernel_launch(void* const* d_in, const int* in_sizes, int n_in,
                              void* d_out, int out_size)
{
    const float2* I = (const float2*)d_in[0];
    float2* spikes = (float2*)d_out;
    float2* series = (float2*)((float*)d_out + (int64_t)B_ * L_ * K_);

    dim3 block(64);
    dim3 grid(NTHREADS / 64);    // 128 blocks
    MultiLIF_kernel<<<grid, block>>>(I, spikes, series);
}